// round 16
// baseline (speedup 1.0000x reference)
#include <cuda_runtime.h>
#include <cuda_bf16.h>
#include <math.h>
#include <stdint.h>

// FeedForwardQuantum v16 — v15 + L1-wavefront cuts:
//  * ASTR 40: conflict-free A-fragment LDS
//  * GEMM2 stores via per-warp smem transpose -> full-line STG.128
//  * m16n8k16 (half the MMA instrs), fragment-packed B tables (LDG.128)
// Math identical to v15 (bf16 hi/lo split, rel_err ~5e-6).

#define DDIM 1024
#define QDIM 16
#define ROWS 64
#define NTH  256
#define NCHK 32
#define ASTR 40
#define PSTR 12
#define OBST 40          // out-buffer row stride (words), ≡8 mod 32

typedef unsigned long long u64;
typedef unsigned int u32;

__device__ u32 g_b1p[16384];   // W1 frags: [s16 64][g 8][c 4][nh 2][j 4]
__device__ u32 g_w2p[16384];   // W2 frags: [gnt 128][lane 32][j 4]

__device__ __forceinline__ u32 pkbf(float a, float b) {
    u32 r; asm("cvt.rn.bf16x2.f32 %0, %1, %2;" : "=r"(r) : "f"(b), "f"(a)); return r;
}
__device__ __forceinline__ float bflo(u32 u) { return __uint_as_float(u << 16); }
__device__ __forceinline__ float bfhi(u32 u) { return __uint_as_float(u & 0xFFFF0000u); }
__device__ __forceinline__ u64 pk(float x, float y) {
    u64 v; asm("mov.b64 %0, {%1,%2};" : "=l"(v) : "f"(x), "f"(y)); return v;
}

__device__ __forceinline__ void mma16(float* d, u32 a0, u32 a1, u32 a2, u32 a3,
                                      u32 b0, u32 b1) {
    asm("mma.sync.aligned.m16n8k16.row.col.f32.bf16.bf16.f32 "
        "{%0,%1,%2,%3}, {%4,%5,%6,%7}, {%8,%9}, {%0,%1,%2,%3};"
        : "+f"(d[0]), "+f"(d[1]), "+f"(d[2]), "+f"(d[3])
        : "r"(a0), "r"(a1), "r"(a2), "r"(a3), "r"(b0), "r"(b1));
}

// ---------------- prep: pack W1 and W2 fragments ----------------
__global__ void ffq_prep(const float* __restrict__ W1, const float* __restrict__ W2) {
    int i = blockIdx.x * 256 + threadIdx.x;
    if (i < 16384) {
        // W1: idx = ((s*8+g)*4+c)*8 + nh*4 + j ; j: {ksg parity, q-tile}
        int s = i >> 8, g = (i >> 5) & 7, c = (i >> 3) & 3;
        int nh = (i >> 2) & 1, j = i & 3;
        int ksg = 2 * s + (j & 1);
        int q   = g + 8 * (j >> 1);
        int k0  = ksg * 8 + c * 2;
        float w0 = W1[(size_t)k0 * QDIM + q];
        float w1 = W1[(size_t)(k0 + 1) * QDIM + q];
        u32 hi = pkbf(w0, w1);
        g_b1p[i] = nh ? pkbf(w0 - bflo(hi), w1 - bfhi(hi)) : hi;
    } else if (i < 32768) {
        // W2: idx = (gnt*32 + lane)*4 + j ; j: {0:hi ks0, 1:hi ks1, 2:lo ks0, 3:lo ks1}
        int t = i - 16384;
        int gnt = t >> 7, lane = (t >> 2) & 31, j = t & 3;
        int g = lane >> 2, c = lane & 3;
        int ks = j & 1, var = j >> 1;
        int q0 = 8 * ks + 2 * c;
        int col = gnt * 8 + g;
        float w0 = W2[(size_t)q0 * DDIM + col];
        float w1 = W2[(size_t)(q0 + 1) * DDIM + col];
        u32 hi = pkbf(w0, w1);
        g_w2p[t] = var ? pkbf(w0 - bflo(hi), w1 - bfhi(hi)) : hi;
    }
}

// ---------------- main ----------------
__global__ void __launch_bounds__(NTH, 3)
ffq_v16(const float* __restrict__ x, const float* __restrict__ b1,
        const float* __restrict__ theta, const float* __restrict__ b2,
        float* __restrict__ out, int nRows)
{
    extern __shared__ u32 smu[];
    u32* A0 = smu;                           // 64*40 = 2560
    u32* A1 = A0 + ROWS * ASTR;              // 2560
    float* ps  = (float*)(A1 + ROWS * ASTR); // 256*12 = 3072
    float* b1s = ps + NTH * PSTR;            // 16
    float* ths = b1s + QDIM;                 // 16
    u32* obase = (u32*)(ths + QDIM);         // 8 warps * 640 = 5120

    const int tid  = threadIdx.x;
    const int row0 = blockIdx.x * ROWS;

    if (tid < QDIM) { b1s[tid] = b1[tid]; ths[tid] = theta[tid]; }

    const int wid  = tid >> 5;
    const int lane = tid & 31;
    const int g    = lane >> 2;
    const int c    = lane & 3;
    const int rg   = wid >> 1;
    const int nh   = wid & 1;

    // ---- x staging: thread owns rows (t>>3), (t>>3)+32; float4 at 4*(t&7) ----
    const int srow = tid >> 3;
    const int c8   = tid & 7;
    int gra = row0 + srow;      if (gra >= nRows) gra = nRows - 1;
    int grb = row0 + srow + 32; if (grb >= nRows) grb = nRows - 1;
    const float* gxa = x + (size_t)gra * DDIM + 4 * c8;
    const float* gxb = x + (size_t)grb * DDIM + 4 * c8;
    u32* dsta0 = A0 + srow * ASTR + 4 * c8;
    u32* dstb0 = A0 + (srow + 32) * ASTR + 4 * c8;

    // prologue: chunk 0
    {
        float4 va = *(const float4*)gxa;
        float4 vb = *(const float4*)gxb;
        u32 h0 = pkbf(va.x, va.y), l0 = pkbf(va.x - bflo(h0), va.y - bfhi(h0));
        u32 h1 = pkbf(va.z, va.w), l1 = pkbf(va.z - bflo(h1), va.w - bfhi(h1));
        *(uint4*)dsta0 = make_uint4(h0, l0, h1, l1);
        h0 = pkbf(vb.x, vb.y); l0 = pkbf(vb.x - bflo(h0), vb.y - bfhi(h0));
        h1 = pkbf(vb.z, vb.w); l1 = pkbf(vb.z - bflo(h1), vb.w - bfhi(h1));
        *(uint4*)dstb0 = make_uint4(h0, l0, h1, l1);
    }
    __syncthreads();

    // ---- GEMM1: d0 = q-low tile, d1 = q-high tile (variant nh) ----
    float d0[4] = {0.f, 0.f, 0.f, 0.f};
    float d1[4] = {0.f, 0.f, 0.f, 0.f};
    const u32 aoff0 = (u32)((16 * rg + g) * ASTR);
    const u32 aoff1 = aoff0 + 8 * ASTR;

    for (int ch = 0; ch < NCHK; ch++) {
        const u32* cur = (ch & 1) ? A1 : A0;

        float4 va, vb;
        if (ch + 1 < NCHK) {
            int dd = (ch + 1) * 32;
            va = *(const float4*)(gxa + dd);
            vb = *(const float4*)(gxb + dd);
        }

#pragma unroll
        for (int s = 0; s < 2; s++) {
            int w0 = 16 * s + 2 * c;
            u64 av0  = *(const u64*)(cur + aoff0 + w0);       // (a0h, a0l)
            u64 av0b = *(const u64*)(cur + aoff0 + w0 + 8);   // (a2h, a2l)
            u64 av1  = *(const u64*)(cur + aoff1 + w0);       // (a1h, a1l)
            u64 av1b = *(const u64*)(cur + aoff1 + w0 + 8);   // (a3h, a3l)
            u32 a0h = (u32)av0,  a0l = (u32)(av0 >> 32);
            u32 a2h = (u32)av0b, a2l = (u32)(av0b >> 32);
            u32 a1h = (u32)av1,  a1l = (u32)(av1 >> 32);
            u32 a3h = (u32)av1b, a3l = (u32)(av1b >> 32);
            int s16 = ch * 2 + s;
            uint4 B = *(const uint4*)(g_b1p + (((s16 * 8 + g) * 4 + c) * 8 + nh * 4));
            mma16(d0, a0h, a1h, a2h, a3h, B.x, B.y);
            mma16(d1, a0h, a1h, a2h, a3h, B.z, B.w);
            mma16(d0, a0l, a1l, a2l, a3l, B.x, B.y);
            mma16(d1, a0l, a1l, a2l, a3l, B.z, B.w);
        }

        if (ch + 1 < NCHK) {
            u32* da = (ch & 1) ? dsta0 : (dsta0 + ROWS * ASTR);
            u32* db = (ch & 1) ? dstb0 : (dstb0 + ROWS * ASTR);
            u32 h0 = pkbf(va.x, va.y), l0 = pkbf(va.x - bflo(h0), va.y - bfhi(h0));
            u32 h1 = pkbf(va.z, va.w), l1 = pkbf(va.z - bflo(h1), va.w - bfhi(h1));
            *(uint4*)da = make_uint4(h0, l0, h1, l1);
            h0 = pkbf(vb.x, vb.y); l0 = pkbf(vb.x - bflo(h0), vb.y - bfhi(h0));
            h1 = pkbf(vb.z, vb.w); l1 = pkbf(vb.z - bflo(h1), vb.w - bfhi(h1));
            *(uint4*)db = make_uint4(h0, l0, h1, l1);
        }
        __syncthreads();
    }

    // ---- exchange h-partials across nh pair, activation -> z ----
    {
        float* myp = ps + (wid * 32 + lane) * PSTR;
        *(float4*)myp       = make_float4(d0[0], d0[1], d1[0], d1[1]);
        *(float4*)(myp + 4) = make_float4(d0[2], d0[3], d1[2], d1[3]);
    }
    __syncthreads();

    float z00, z01, z08, z09, z10, z11, z18, z19;
    {
        const float* pp = ps + ((wid ^ 1) * 32 + lane) * PSTR;
        float4 q0 = *(const float4*)pp;
        float4 q1 = *(const float4*)(pp + 4);
        float2 b1a = *(const float2*)(b1s + 2 * c);
        float2 b1c = *(const float2*)(b1s + 8 + 2 * c);
        float2 tha = *(const float2*)(ths + 2 * c);
        float2 thc = *(const float2*)(ths + 8 + 2 * c);
        z00 = __cosf(fmaxf(d0[0] + q0.x + b1a.x, 0.f) + tha.x);
        z01 = __cosf(fmaxf(d0[1] + q0.y + b1a.y, 0.f) + tha.y);
        z08 = __cosf(fmaxf(d1[0] + q0.z + b1c.x, 0.f) + thc.x);
        z09 = __cosf(fmaxf(d1[1] + q0.w + b1c.y, 0.f) + thc.y);
        z10 = __cosf(fmaxf(d0[2] + q1.x + b1a.x, 0.f) + tha.x);
        z11 = __cosf(fmaxf(d0[3] + q1.y + b1a.y, 0.f) + tha.y);
        z18 = __cosf(fmaxf(d1[2] + q1.z + b1c.x, 0.f) + thc.x);
        z19 = __cosf(fmaxf(d1[3] + q1.w + b1c.y, 0.f) + thc.y);
    }

    // ---- z -> A fragments (hi + lo) ----
    u32 ah00 = pkbf(z00, z01), ah01 = pkbf(z08, z09);
    u32 ah10 = pkbf(z10, z11), ah11 = pkbf(z18, z19);
    u32 al00 = pkbf(z00 - bflo(ah00), z01 - bfhi(ah00));
    u32 al01 = pkbf(z08 - bflo(ah01), z09 - bfhi(ah01));
    u32 al10 = pkbf(z10 - bflo(ah10), z11 - bfhi(ah10));
    u32 al11 = pkbf(z18 - bflo(ah11), z19 - bfhi(ah11));

    // ---- GEMM2: warp (rg,nh) -> rows 16rg..+15, cols nh*512..+511 ----
    // 4-nt groups; results transposed through per-warp smem buffer, then
    // full-line STG.128 (4 rows x 128B per instruction).
    const int r0w = row0 + 16 * rg;          // warp's first global row
    u32* ob = obase + wid * (16 * OBST);

    for (int grp = 0; grp < 16; grp++) {
#pragma unroll
        for (int ntl = 0; ntl < 4; ntl++) {
            int gnt = nh * 64 + grp * 4 + ntl;
            uint4 B = *(const uint4*)(g_w2p + (gnt * 32 + lane) * 4);
            float2 b2f = *(const float2*)(b2 + 8 * gnt + 2 * c);
            float e[4] = {b2f.x, b2f.y, b2f.x, b2f.y};
            mma16(e, ah00, ah10, ah01, ah11, B.x, B.y);
            mma16(e, al00, al10, al01, al11, B.x, B.y);
            mma16(e, ah00, ah10, ah01, ah11, B.z, B.w);
            *(u64*)(ob + g * OBST + ntl * 8 + 2 * c)       = pk(e[0], e[1]);
            *(u64*)(ob + (8 + g) * OBST + ntl * 8 + 2 * c) = pk(e[2], e[3]);
        }
        __syncwarp();
        int col0 = 512 * nh + 32 * grp;
#pragma unroll
        for (int i = 0; i < 4; i++) {
            int brow = 4 * i + (lane >> 3);
            uint4 v = *(const uint4*)(ob + brow * OBST + 4 * (lane & 7));
            int grow = r0w + brow;
            if (grow < nRows)
                *(uint4*)((u32*)out + (size_t)grow * DDIM + col0 + 4 * (lane & 7)) = v;
        }
        __syncwarp();
    }
}

extern "C" void kernel_launch(void* const* d_in, const int* in_sizes, int n_in,
                              void* d_out, int out_size) {
    const float* x     = (const float*)d_in[0];
    const float* W1    = (const float*)d_in[1];
    const float* b1    = (const float*)d_in[2];
    const float* theta = (const float*)d_in[3];
    const float* W2    = (const float*)d_in[4];
    const float* b2    = (const float*)d_in[5];
    float* out = (float*)d_out;

    int nRows = in_sizes[0] / DDIM;                    // 32768
    int grid  = (nRows + ROWS - 1) / ROWS;             // 512

    // 2*2560 + 3072 + 32 + 5120 = 13344 words = 53.4KB
    size_t smem = (size_t)(2 * ROWS * ASTR + NTH * PSTR + 2 * QDIM + 8 * 16 * OBST)
                  * sizeof(u32);
    static int attr_set = 0;
    if (!attr_set) {
        cudaFuncSetAttribute(ffq_v16, cudaFuncAttributeMaxDynamicSharedMemorySize,
                             (int)smem);
        attr_set = 1;
    }

    ffq_prep<<<128, 256>>>(W1, W2);
    ffq_v16<<<grid, NTH, smem>>>(x, b1, theta, b2, out, nRows);
}

// round 17
// speedup vs baseline: 1.2182x; 1.2182x over previous
#include <cuda_runtime.h>
#include <cuda_bf16.h>
#include <math.h>
#include <stdint.h>

// FeedForwardQuantum v17 — v15 base (verified 4 CTAs/SM) with:
//  * ASTR 40: conflict-free A-fragment LDS (banks 8g+2c all distinct)
//  * GEMM2: packed uint4 W2-fragment table + m16n8k16 (verified in v16)
//  * direct STG stores (v15 style), k8 GEMM1 (reg-light), launch_bounds(,4)
//   out = cos(relu(x@W1 + b1) + theta) @ W2 + b2

#define DDIM 1024
#define QDIM 16
#define ROWS 64
#define NTH  256
#define NCHK 32
#define ASTR 40
#define PSTR 12

typedef unsigned long long u64;
typedef unsigned int u32;

__device__ u32 g_b1p[16384];   // W1 frags: [ksg 128][n8 8][kp 4][nt 4]
__device__ u32 g_w2p[16384];   // W2 frags: [gnt 128][lane 32][j 4]

__device__ __forceinline__ u32 pkbf(float a, float b) {
    u32 r; asm("cvt.rn.bf16x2.f32 %0, %1, %2;" : "=r"(r) : "f"(b), "f"(a)); return r;
}
__device__ __forceinline__ float bflo(u32 u) { return __uint_as_float(u << 16); }
__device__ __forceinline__ float bfhi(u32 u) { return __uint_as_float(u & 0xFFFF0000u); }

__device__ __forceinline__ void mma8(float* d, u32 a0, u32 a1, u32 b) {
    asm("mma.sync.aligned.m16n8k8.row.col.f32.bf16.bf16.f32 "
        "{%0,%1,%2,%3}, {%4,%5}, {%6}, {%0,%1,%2,%3};"
        : "+f"(d[0]), "+f"(d[1]), "+f"(d[2]), "+f"(d[3])
        : "r"(a0), "r"(a1), "r"(b));
}
__device__ __forceinline__ void mma16(float* d, u32 a0, u32 a1, u32 a2, u32 a3,
                                      u32 b0, u32 b1) {
    asm("mma.sync.aligned.m16n8k16.row.col.f32.bf16.bf16.f32 "
        "{%0,%1,%2,%3}, {%4,%5,%6,%7}, {%8,%9}, {%0,%1,%2,%3};"
        : "+f"(d[0]), "+f"(d[1]), "+f"(d[2]), "+f"(d[3])
        : "r"(a0), "r"(a1), "r"(a2), "r"(a3), "r"(b0), "r"(b1));
}

// ---------------- prep: pack W1 and W2 fragments ----------------
__global__ void ffq_prep(const float* __restrict__ W1, const float* __restrict__ W2) {
    int i = blockIdx.x * 256 + threadIdx.x;
    if (i < 16384) {
        // W1 frags (v15-verified): [ksg][n8][kp][nt]; q = n8 + 8*(nt&1); nt>>1 hi/lo
        int ksg = i >> 7, rem = i & 127;
        int n8 = rem >> 4, r2 = rem & 15, kp = r2 >> 2, nt = r2 & 3;
        int q = n8 + 8 * (nt & 1);
        int hilo = nt >> 1;
        int k0 = ksg * 8 + kp * 2;
        float w0 = W1[(size_t)k0 * QDIM + q];
        float w1 = W1[(size_t)(k0 + 1) * QDIM + q];
        u32 hi = pkbf(w0, w1);
        g_b1p[i] = hilo ? pkbf(w0 - bflo(hi), w1 - bfhi(hi)) : hi;
    } else if (i < 32768) {
        // W2 frags (v16-verified): idx = (gnt*32+lane)*4 + j ;
        // j: {0: hi ks0, 1: hi ks1, 2: lo ks0, 3: lo ks1}
        int t = i - 16384;
        int gnt = t >> 7, lane = (t >> 2) & 31, j = t & 3;
        int g = lane >> 2, c = lane & 3;
        int ks = j & 1, var = j >> 1;
        int q0 = 8 * ks + 2 * c;
        int col = gnt * 8 + g;
        float w0 = W2[(size_t)q0 * DDIM + col];
        float w1 = W2[(size_t)(q0 + 1) * DDIM + col];
        u32 hi = pkbf(w0, w1);
        g_w2p[t] = var ? pkbf(w0 - bflo(hi), w1 - bfhi(hi)) : hi;
    }
}

// ---------------- main ----------------
__global__ void __launch_bounds__(NTH, 4)
ffq_v17(const float* __restrict__ x, const float* __restrict__ b1,
        const float* __restrict__ theta, const float* __restrict__ b2,
        float* __restrict__ out, int nRows)
{
    extern __shared__ u32 smu[];
    u32* A0 = smu;                           // 64*40 = 2560
    u32* A1 = A0 + ROWS * ASTR;              // 2560
    float* ps  = (float*)(A1 + ROWS * ASTR); // 256*12 = 3072
    float* b1s = ps + NTH * PSTR;            // 16
    float* ths = b1s + QDIM;                 // 16

    const int tid  = threadIdx.x;
    const int row0 = blockIdx.x * ROWS;

    if (tid < QDIM) { b1s[tid] = b1[tid]; ths[tid] = theta[tid]; }

    const int wid  = tid >> 5;
    const int lane = tid & 31;
    const int g    = lane >> 2;
    const int c    = lane & 3;
    const int rg   = wid >> 1;               // rows 16rg..16rg+15
    const int nh   = wid & 1;                // W1 hi/lo partial; GEMM2 col half

    // ---- x staging: thread owns rows (t>>3), (t>>3)+32; float4 at 4*(t&7) ----
    const int srow = tid >> 3;
    const int c8   = tid & 7;
    int gra = row0 + srow;      if (gra >= nRows) gra = nRows - 1;
    int grb = row0 + srow + 32; if (grb >= nRows) grb = nRows - 1;
    const float* gxa = x + (size_t)gra * DDIM + 4 * c8;
    const float* gxb = x + (size_t)grb * DDIM + 4 * c8;
    u32* dsta0 = A0 + srow * ASTR + 4 * c8;
    u32* dstb0 = A0 + (srow + 32) * ASTR + 4 * c8;

    // prologue: chunk 0
    {
        float4 va = *(const float4*)gxa;
        float4 vb = *(const float4*)gxb;
        u32 h0 = pkbf(va.x, va.y), l0 = pkbf(va.x - bflo(h0), va.y - bfhi(h0));
        u32 h1 = pkbf(va.z, va.w), l1 = pkbf(va.z - bflo(h1), va.w - bfhi(h1));
        *(uint4*)dsta0 = make_uint4(h0, l0, h1, l1);
        h0 = pkbf(vb.x, vb.y); l0 = pkbf(vb.x - bflo(h0), vb.y - bfhi(h0));
        h1 = pkbf(vb.z, vb.w); l1 = pkbf(vb.z - bflo(h1), vb.w - bfhi(h1));
        *(uint4*)dstb0 = make_uint4(h0, l0, h1, l1);
    }
    __syncthreads();

    // ---- GEMM1 (v15-verified, k8): d0 = q-low tile, d1 = q-high (variant nh) ----
    float d0[4] = {0.f, 0.f, 0.f, 0.f};
    float d1[4] = {0.f, 0.f, 0.f, 0.f};
    const u32 aoff0 = (u32)((16 * rg + g) * ASTR);
    const u32 aoff1 = aoff0 + 8 * ASTR;

    for (int ch = 0; ch < NCHK; ch++) {
        const u32* cur = (ch & 1) ? A1 : A0;

        float4 va, vb;
        if (ch + 1 < NCHK) {
            int dd = (ch + 1) * 32;
            va = *(const float4*)(gxa + dd);
            vb = *(const float4*)(gxb + dd);
        }

#pragma unroll
        for (int ks = 0; ks < 4; ks++) {
            int kloc = (ks * 4 + c) * 2;
            u64 av0 = *(const u64*)(cur + aoff0 + kloc);   // lo32=hi frag, hi32=lo
            u64 av1 = *(const u64*)(cur + aoff1 + kloc);
            u32 a0h = (u32)av0, a0l = (u32)(av0 >> 32);
            u32 a1h = (u32)av1, a1l = (u32)(av1 >> 32);
            int ksg = ch * 4 + ks;
            uint2 b = *(const uint2*)(g_b1p + ksg * 128 + g * 16 + c * 4 + 2 * nh);
            mma8(d0, a0h, a1h, b.x);
            mma8(d1, a0h, a1h, b.y);
            mma8(d0, a0l, a1l, b.x);
            mma8(d1, a0l, a1l, b.y);
        }

        if (ch + 1 < NCHK) {
            u32* da = (ch & 1) ? dsta0 : (dsta0 + ROWS * ASTR);
            u32* db = (ch & 1) ? dstb0 : (dstb0 + ROWS * ASTR);
            u32 h0 = pkbf(va.x, va.y), l0 = pkbf(va.x - bflo(h0), va.y - bfhi(h0));
            u32 h1 = pkbf(va.z, va.w), l1 = pkbf(va.z - bflo(h1), va.w - bfhi(h1));
            *(uint4*)da = make_uint4(h0, l0, h1, l1);
            h0 = pkbf(vb.x, vb.y); l0 = pkbf(vb.x - bflo(h0), vb.y - bfhi(h0));
            h1 = pkbf(vb.z, vb.w); l1 = pkbf(vb.z - bflo(h1), vb.w - bfhi(h1));
            *(uint4*)db = make_uint4(h0, l0, h1, l1);
        }
        __syncthreads();
    }

    // ---- exchange h-partials across nh pair, activation -> z ----
    {
        float* myp = ps + (wid * 32 + lane) * PSTR;
        *(float4*)myp       = make_float4(d0[0], d0[1], d1[0], d1[1]);
        *(float4*)(myp + 4) = make_float4(d0[2], d0[3], d1[2], d1[3]);
    }
    __syncthreads();

    float z00, z01, z08, z09, z10, z11, z18, z19;
    {
        const float* pp = ps + ((wid ^ 1) * 32 + lane) * PSTR;
        float4 q0 = *(const float4*)pp;
        float4 q1 = *(const float4*)(pp + 4);
        float2 b1a = *(const float2*)(b1s + 2 * c);
        float2 b1c = *(const float2*)(b1s + 8 + 2 * c);
        float2 tha = *(const float2*)(ths + 2 * c);
        float2 thc = *(const float2*)(ths + 8 + 2 * c);
        z00 = __cosf(fmaxf(d0[0] + q0.x + b1a.x, 0.f) + tha.x);
        z01 = __cosf(fmaxf(d0[1] + q0.y + b1a.y, 0.f) + tha.y);
        z08 = __cosf(fmaxf(d1[0] + q0.z + b1c.x, 0.f) + thc.x);
        z09 = __cosf(fmaxf(d1[1] + q0.w + b1c.y, 0.f) + thc.y);
        z10 = __cosf(fmaxf(d0[2] + q1.x + b1a.x, 0.f) + tha.x);
        z11 = __cosf(fmaxf(d0[3] + q1.y + b1a.y, 0.f) + tha.y);
        z18 = __cosf(fmaxf(d1[2] + q1.z + b1c.x, 0.f) + thc.x);
        z19 = __cosf(fmaxf(d1[3] + q1.w + b1c.y, 0.f) + thc.y);
    }

    // ---- z -> A fragments (hi + lo) ----
    u32 ah00 = pkbf(z00, z01), ah01 = pkbf(z08, z09);   // row r0: k-low, k-high
    u32 ah10 = pkbf(z10, z11), ah11 = pkbf(z18, z19);   // row r1
    u32 al00 = pkbf(z00 - bflo(ah00), z01 - bfhi(ah00));
    u32 al01 = pkbf(z08 - bflo(ah01), z09 - bfhi(ah01));
    u32 al10 = pkbf(z10 - bflo(ah10), z11 - bfhi(ah10));
    u32 al11 = pkbf(z18 - bflo(ah11), z19 - bfhi(ah11));

    // ---- GEMM2 (v16-verified math, v15-style stores) ----
    const int r0g = row0 + 16 * rg + g;
    const int r1g = r0g + 8;
    float* out0 = out + (size_t)r0g * DDIM + 2 * c;
    float* out1 = out + (size_t)r1g * DDIM + 2 * c;

    for (int nt = 0; nt < 64; nt++) {
        int gnt = nh * 64 + nt;
        uint4 B = *(const uint4*)(g_w2p + (gnt * 32 + lane) * 4);
        float2 b2f = *(const float2*)(b2 + 8 * gnt + 2 * c);
        float e[4] = {b2f.x, b2f.y, b2f.x, b2f.y};
        mma16(e, ah00, ah10, ah01, ah11, B.x, B.y);   // z_hi @ w_hi
        mma16(e, al00, al10, al01, al11, B.x, B.y);   // z_lo @ w_hi
        mma16(e, ah00, ah10, ah01, ah11, B.z, B.w);   // z_hi @ w_lo
        if (r0g < nRows)
            *(float2*)(out0 + 8 * gnt) = make_float2(e[0], e[1]);
        if (r1g < nRows)
            *(float2*)(out1 + 8 * gnt) = make_float2(e[2], e[3]);
    }
}

extern "C" void kernel_launch(void* const* d_in, const int* in_sizes, int n_in,
                              void* d_out, int out_size) {
    const float* x     = (const float*)d_in[0];
    const float* W1    = (const float*)d_in[1];
    const float* b1    = (const float*)d_in[2];
    const float* theta = (const float*)d_in[3];
    const float* W2    = (const float*)d_in[4];
    const float* b2    = (const float*)d_in[5];
    float* out = (float*)d_out;

    int nRows = in_sizes[0] / DDIM;                    // 32768
    int grid  = (nRows + ROWS - 1) / ROWS;             // 512

    // 2*2560 + 3072 + 32 = 8224 words = 32.9KB -> 4 CTAs/SM
    size_t smem = (size_t)(2 * ROWS * ASTR + NTH * PSTR + 2 * QDIM) * sizeof(u32);

    ffq_prep<<<128, 256>>>(W1, W2);
    ffq_v17<<<grid, NTH, smem>>>(x, b1, theta, b2, out, nRows);
}